// round 15
// baseline (speedup 1.0000x reference)
#include <cuda_runtime.h>
#include <cuda_fp16.h>
#include <math.h>

// Problem constants
#define Jc 166
#define Rc 864
#define Oc 8
#define Bc 128
#define BT 8            // batches per CTA (2 warps per batch)
#define TT 512          // threads per CTA, 16 warps -> 64-reg ceiling @2 CTAs/SM

#define W_ELEMS (Jc * Rc * Oc * 4)   // 4,589,568
#define U_ELEMS (Bc * Rc * 4)        //   442,368
#define NROUTES (Jc * Rc)            //   143,424

#define LOG2E 1.4426950408889634f

// smem layout (uint4 units for uh, then aux)
#define UH_U4    (BT * Rc)                    // 6912 uint4 = 110592 B
#define AUX0_U4  UH_U4                        // [8][2] uint4 pass0 partials
#define AUX1_F   ((AUX0_U4 + 16) * 4)         // float idx: [8][2][12] pass1
#define AUX2_F   (AUX1_F + 192)               // float idx: [8][2][12] pass2
#define SMEM_BYTES ((AUX2_F + 192) * 4)       // 112384 B

// fp16 copies of inputs (static device buffers: no allocation)
// W16g: per route (j*Rc+r), 4 uint4; uint4 q holds half2 pairs
//   .x=(W[2q][0],W[2q+1][0]) .y=(i=1) .z=(i=2) .w=(i=3)
__device__ uint4  W16g[NROUTES * 4];   // 9.18 MB
__device__ __half u16g[U_ELEMS];       // 0.88 MB

__device__ __forceinline__ unsigned int pk2(float a, float b) {
    __half2 h = __floats2half2_rn(a, b);
    return *reinterpret_cast<unsigned int*>(&h);
}
__device__ __forceinline__ float2 up2(unsigned int v) {
    __half2 h = *reinterpret_cast<__half2*>(&v);
    return __half22float2(h);
}
__device__ __forceinline__ __half2 h2(unsigned int v) {
    return *reinterpret_cast<__half2*>(&v);
}
__device__ __forceinline__ unsigned int u32(__half2 v) {
    return *reinterpret_cast<unsigned int*>(&v);
}
__device__ __forceinline__ unsigned int hadd2u(unsigned int a, unsigned int b) {
    __half2 r = __hadd2(h2(a), h2(b));
    return u32(r);
}

// butterfly-reduce N floats across the warp (all lanes get result)
template<int N>
__device__ __forceinline__ void wredN(float* p) {
#pragma unroll
    for (int s = 16; s; s >>= 1)
#pragma unroll
        for (int q = 0; q < N; q++)
            p[q] += __shfl_xor_sync(0xffffffffu, p[q], s);
}

// ------------------- prep: fp32 -> fp16 (W o-pair-interleaved, u flat) -----
__global__ void __launch_bounds__(256)
prep_kernel(const float* __restrict__ W, const float* __restrict__ u)
{
    const int idx = blockIdx.x * blockDim.x + threadIdx.x;
    if (idx < NROUTES) {
        const float4* f4 = (const float4*)(W + (size_t)idx * 32);
#pragma unroll
        for (int q = 0; q < 4; q++) {
            const float4 lo = f4[2 * q];       // o = 2q,   i = 0..3
            const float4 hi = f4[2 * q + 1];   // o = 2q+1, i = 0..3
            uint4 o;
            o.x = pk2(lo.x, hi.x);
            o.y = pk2(lo.y, hi.y);
            o.z = pk2(lo.z, hi.z);
            o.w = pk2(lo.w, hi.w);
            W16g[(size_t)idx * 4 + q] = o;
        }
    }
    if (idx < U_ELEMS / 8) {
        const float4* p = (const float4*)u + (size_t)idx * 2;
        const float4 a = p[0], b = p[1];
        uint4 o;
        o.x = pk2(a.x, a.y); o.y = pk2(a.z, a.w);
        o.z = pk2(b.x, b.y); o.w = pk2(b.z, b.w);
        ((uint4*)u16g)[idx] = o;
    }
}

// gen one route r via HFMA2 (W stays packed; R8-proven math)
__device__ __forceinline__ void gen_route(const uint4* __restrict__ W4,
                                          const uint2* __restrict__ u2p,
                                          uint4* __restrict__ uh,
                                          int r, int b0)
{
    const uint4 w0 = W4[(size_t)r * 4 + 0];
    const uint4 w1 = W4[(size_t)r * 4 + 1];
    const uint4 w2 = W4[(size_t)r * 4 + 2];
    const uint4 w3 = W4[(size_t)r * 4 + 3];
#pragma unroll
    for (int b = 0; b < BT; b++) {
        const uint2 uu = u2p[(size_t)(b0 + b) * Rc + r];
        const __half2 x01 = h2(uu.x), x23 = h2(uu.y);
        const __half2 bh0 = __low2half2(x01),  bh1 = __high2half2(x01);
        const __half2 bh2 = __low2half2(x23),  bh3 = __high2half2(x23);
        uint4 pkv;
        pkv.x = u32(__hfma2(h2(w0.w), bh3, __hfma2(h2(w0.z), bh2,
                  __hfma2(h2(w0.y), bh1, __hmul2(h2(w0.x), bh0)))));
        pkv.y = u32(__hfma2(h2(w1.w), bh3, __hfma2(h2(w1.z), bh2,
                  __hfma2(h2(w1.y), bh1, __hmul2(h2(w1.x), bh0)))));
        pkv.z = u32(__hfma2(h2(w2.w), bh3, __hfma2(h2(w2.z), bh2,
                  __hfma2(h2(w2.y), bh1, __hmul2(h2(w2.x), bh0)))));
        pkv.w = u32(__hfma2(h2(w3.w), bh3, __hfma2(h2(w3.z), bh2,
                  __hfma2(h2(w3.y), bh1, __hmul2(h2(w3.x), bh0)))));
        uh[b * Rc + r] = pkv;
    }
}

// ------------------------------ main kernel ------------------------------
__global__ void __launch_bounds__(TT, 2)
digitcaps_kernel(float* __restrict__ out)
{
    extern __shared__ uint4 uh[];               // [BT][Rc]
    uint4* aux0 = uh + AUX0_U4;                 // [8][2] uint4
    float* auxf = (float*)uh;                   // float view for aux1/aux2

    const int g    = blockIdx.x;
    const int j    = blockIdx.y;
    const int b0   = g * BT;
    const int t    = threadIdx.x;
    const int warp = t >> 5;
    const int lane = t & 31;

    const uint4* __restrict__ W4  = W16g + (size_t)j * Rc * 4;
    const uint2* __restrict__ u2p = (const uint2*)u16g;

    // ====== gen: u_hat -> smem (HFMA2); routes t and t+512 ====================
    gen_route(W4, u2p, uh, t, b0);
    if (t < Rc - TT)                              // threads 0..351 cover 512..863
        gen_route(W4, u2p, uh, t + TT, b0);
    __syncthreads();

    // ============== routing: warps (b, b+8) co-own batch b ====================
    const int b    = warp & 7;
    const int sub  = warp >> 3;                   // 0 or 1
    const int niter = 14 - sub;                   // sub0: 14 routes, sub1: 13
    const uint4* __restrict__ base = uh + b * Rc + sub * 32 + lane;
    const int barid = b + 1;

    // ---- pass 0 (half2 accumulate): s0 = mean_r u_hat ; v0 = squash ----
    unsigned int h0 = 0u, h1 = 0u, hv2 = 0u, h3 = 0u;
    for (int i = 0; i < niter; i++) {
        const uint4 v = base[i * 64];
        h0 = hadd2u(h0, v.x); h1 = hadd2u(h1, v.y);
        hv2 = hadd2u(hv2, v.z); h3 = hadd2u(h3, v.w);
    }
#pragma unroll
    for (int s = 16; s; s >>= 1) {
        h0 = hadd2u(h0, __shfl_xor_sync(0xffffffffu, h0, s));
        h1 = hadd2u(h1, __shfl_xor_sync(0xffffffffu, h1, s));
        hv2 = hadd2u(hv2, __shfl_xor_sync(0xffffffffu, hv2, s));
        h3 = hadd2u(h3, __shfl_xor_sync(0xffffffffu, h3, s));
    }
    if (lane == 0) aux0[b * 2 + sub] = make_uint4(h0, h1, hv2, h3);
    asm volatile("bar.sync %0, %1;" :: "r"(barid), "r"(64) : "memory");

    float v0[Oc], v0s[Oc];
    {
        const uint4 pa = aux0[b * 2 + 0];
        const uint4 pb = aux0[b * 2 + 1];
        const unsigned int c0 = hadd2u(pa.x, pb.x), c1 = hadd2u(pa.y, pb.y);
        const unsigned int c2 = hadd2u(pa.z, pb.z), c3 = hadd2u(pa.w, pb.w);
        const float2 f0 = up2(c0), f1 = up2(c1), f2 = up2(c2), f3 = up2(c3);
        float s[Oc] = { f0.x, f0.y, f1.x, f1.y, f2.x, f2.y, f3.x, f3.y };
        float sq = 0.f;
#pragma unroll
        for (int o = 0; o < Oc; o++) { s[o] *= (1.0f / (float)Rc); sq += s[o] * s[o]; }
        const float scl = sqrtf(sq) / (1.f + sq);
#pragma unroll
        for (int o = 0; o < Oc; o++) {
            v0[o]  = s[o] * scl;
            v0s[o] = v0[o] * LOG2E;
        }
    }

    // ---- pass 1: e = 2^(<uh,v0s>) ; weighted sums -> v1 ----
    float p[9];
#pragma unroll
    for (int q = 0; q < 9; q++) p[q] = 0.f;
    for (int i = 0; i < niter; i++) {
        const uint4 v = base[i * 64];
        const float2 f0 = up2(v.x), f1 = up2(v.y), f2 = up2(v.z), f3 = up2(v.w);
        const float a = f0.x * v0s[0] + f0.y * v0s[1] + f1.x * v0s[2] + f1.y * v0s[3]
                      + f2.x * v0s[4] + f2.y * v0s[5] + f3.x * v0s[6] + f3.y * v0s[7];
        const float e = exp2f(a);
        p[8] += e;
        p[0] += e * f0.x; p[1] += e * f0.y;
        p[2] += e * f1.x; p[3] += e * f1.y;
        p[4] += e * f2.x; p[5] += e * f2.y;
        p[6] += e * f3.x; p[7] += e * f3.y;
    }
    wredN<9>(p);
    if (lane < 9) auxf[AUX1_F + (b * 2 + sub) * 12 + lane] = p[lane];
    asm volatile("bar.sync %0, %1;" :: "r"(barid), "r"(64) : "memory");
    {
        const float* part = auxf + AUX1_F + (b * 2 + (1 - sub)) * 12;
#pragma unroll
        for (int q = 0; q < 9; q++) p[q] += part[q];
    }
    float vss[Oc];  // (v0 + v1) * log2(e)   [b2 = <uh, v0+v1>]
    {
        const float inv = __fdividef(1.f, p[8]);
        float sq = 0.f;
#pragma unroll
        for (int o = 0; o < Oc; o++) { p[o] *= inv; sq += p[o] * p[o]; }
        const float scl = sqrtf(sq) / (1.f + sq);
#pragma unroll
        for (int o = 0; o < Oc; o++) vss[o] = (v0[o] + p[o] * scl) * LOG2E;
    }

    // ---- pass 2: e = 2^(<uh,vss>) ; weighted sums -> v2 -> out ----
#pragma unroll
    for (int q = 0; q < 9; q++) p[q] = 0.f;
    for (int i = 0; i < niter; i++) {
        const uint4 v = base[i * 64];
        const float2 f0 = up2(v.x), f1 = up2(v.y), f2 = up2(v.z), f3 = up2(v.w);
        const float a = f0.x * vss[0] + f0.y * vss[1] + f1.x * vss[2] + f1.y * vss[3]
                      + f2.x * vss[4] + f2.y * vss[5] + f3.x * vss[6] + f3.y * vss[7];
        const float e = exp2f(a);
        p[8] += e;
        p[0] += e * f0.x; p[1] += e * f0.y;
        p[2] += e * f1.x; p[3] += e * f1.y;
        p[4] += e * f2.x; p[5] += e * f2.y;
        p[6] += e * f3.x; p[7] += e * f3.y;
    }
    wredN<9>(p);
    if (lane < 9) auxf[AUX2_F + (b * 2 + sub) * 12 + lane] = p[lane];
    asm volatile("bar.sync %0, %1;" :: "r"(barid), "r"(64) : "memory");
    if (sub == 0) {
        const float* part = auxf + AUX2_F + (b * 2 + 1) * 12;
#pragma unroll
        for (int q = 0; q < 9; q++) p[q] += part[q];
        const float inv = __fdividef(1.f, p[8]);
        float sq = 0.f;
#pragma unroll
        for (int o = 0; o < Oc; o++) { p[o] *= inv; sq += p[o] * p[o]; }
        const float scl = sqrtf(sq) / (1.f + sq);
        if (lane < Oc)
            out[((size_t)(b0 + b) * Jc + j) * Oc + lane] = p[lane] * scl;
    }
}

extern "C" void kernel_launch(void* const* d_in, const int* in_sizes, int n_in,
                              void* d_out, int out_size)
{
    const float* u = (const float*)d_in[0];
    const float* W = (const float*)d_in[1];
    if (n_in >= 2 && in_sizes[0] > in_sizes[1]) {   // defensive order check
        const float* tmp = u; u = W; W = tmp;
    }

    cudaFuncSetAttribute(digitcaps_kernel,
                         cudaFuncAttributeMaxDynamicSharedMemorySize, SMEM_BYTES);

    // 1) convert W (o-pair-interleaved) and u to fp16 staging buffers
    prep_kernel<<<(NROUTES + 255) / 256, 256>>>(W, u);
    // 2) fused capsule-routing kernel
    dim3 grid(Bc / BT, Jc);   // (16, 166)
    digitcaps_kernel<<<grid, TT, SMEM_BYTES>>>((float*)d_out);
}

// round 16
// speedup vs baseline: 1.1268x; 1.1268x over previous
#include <cuda_runtime.h>
#include <cuda_fp16.h>
#include <math.h>

// Problem constants
#define Jc 166
#define Rc 864
#define Oc 8
#define Bc 128
#define BT 8            // batches per CTA (one per warp, warps 0-7)
#define TT 288          // threads per CTA (864/3), 9 warps
#define KR 3            // routes per thread in gen
#define RW 27           // routes per lane in routing (864/32)

#define W_ELEMS (Jc * Rc * Oc * 4)   // 4,589,568
#define U_ELEMS (Bc * Rc * 4)        //   442,368

#define SMEM_BYTES (BT * Rc * 16)    // u_hat fp16-packed uint4: 110592 B
#define LOG2E 1.4426950408889634f

// fp16 copies of the inputs (static device buffers: no allocation)
__device__ __half W16g[W_ELEMS];     // 9.18 MB, layout identical to W
__device__ __half u16g[U_ELEMS];     // 0.88 MB, layout identical to u

__device__ __forceinline__ unsigned int pk2(float a, float b) {
    __half2 h = __floats2half2_rn(a, b);
    return *reinterpret_cast<unsigned int*>(&h);
}
__device__ __forceinline__ float2 up2(unsigned int v) {
    __half2 h = *reinterpret_cast<__half2*>(&v);
    return __half22float2(h);
}
__device__ __forceinline__ unsigned int hadd2u(unsigned int a, unsigned int b) {
    __half2 ha = *reinterpret_cast<__half2*>(&a);
    __half2 hb = *reinterpret_cast<__half2*>(&b);
    __half2 r = __hadd2(ha, hb);
    return *reinterpret_cast<unsigned int*>(&r);
}
// guaranteed single MUFU.EX2 regardless of fast-math flags
__device__ __forceinline__ float ex2f(float x) {
    float r;
    asm("ex2.approx.ftz.f32 %0, %1;" : "=f"(r) : "f"(x));
    return r;
}

// butterfly-reduce N floats across the warp (all lanes get result)
template<int N>
__device__ __forceinline__ void wredN(float* p) {
#pragma unroll
    for (int s = 16; s; s >>= 1)
#pragma unroll
        for (int q = 0; q < N; q++)
            p[q] += __shfl_xor_sync(0xffffffffu, p[q], s);
}

// ------------------- prep: fp32 -> fp16 for W and u -------------------
__global__ void __launch_bounds__(256)
prep_kernel(const float* __restrict__ W, const float* __restrict__ u)
{
    const int idx = blockIdx.x * blockDim.x + threadIdx.x;
    if (idx < W_ELEMS / 8) {
        const float4* p = (const float4*)W + (size_t)idx * 2;
        const float4 a = p[0], b = p[1];
        uint4 o;
        o.x = pk2(a.x, a.y); o.y = pk2(a.z, a.w);
        o.z = pk2(b.x, b.y); o.w = pk2(b.z, b.w);
        ((uint4*)W16g)[idx] = o;
    }
    if (idx < U_ELEMS / 8) {
        const float4* p = (const float4*)u + (size_t)idx * 2;
        const float4 a = p[0], b = p[1];
        uint4 o;
        o.x = pk2(a.x, a.y); o.y = pk2(a.z, a.w);
        o.z = pk2(b.x, b.y); o.w = pk2(b.z, b.w);
        ((uint4*)u16g)[idx] = o;
    }
}

// ------------------------------ main kernel ------------------------------
__global__ void __launch_bounds__(TT, 2)
digitcaps_kernel(float* __restrict__ out)
{
    extern __shared__ uint4 uh[];              // [BT][Rc]

    const int g    = blockIdx.x;
    const int j    = blockIdx.y;
    const int b0   = g * BT;
    const int t    = threadIdx.x;
    const int warp = t >> 5;
    const int lane = t & 31;

    // W16 route r of capsule j: 32 halves = 4 uint4 at index (j*Rc + r)*4
    const uint4* __restrict__ W4 = ((const uint4*)W16g) + (size_t)j * Rc * 4;
    // u16 (b, r): 4 halves = 1 uint2 at index b*Rc + r
    const uint2* __restrict__ u2p = (const uint2*)u16g;

    // ====== gen: u_hat -> smem (fp16 packed), fp32 math (R6 verbatim) =========
#pragma unroll
    for (int k = 0; k < KR; k++) {
        const int r = t + k * TT;
        float w[Oc][4];
#pragma unroll
        for (int q = 0; q < 4; q++) {
            const uint4 wq = W4[(size_t)r * 4 + q];
            const float2 a0 = up2(wq.x), a1 = up2(wq.y);   // o = 2q
            const float2 c0 = up2(wq.z), c1 = up2(wq.w);   // o = 2q+1
            w[2 * q + 0][0] = a0.x; w[2 * q + 0][1] = a0.y;
            w[2 * q + 0][2] = a1.x; w[2 * q + 0][3] = a1.y;
            w[2 * q + 1][0] = c0.x; w[2 * q + 1][1] = c0.y;
            w[2 * q + 1][2] = c1.x; w[2 * q + 1][3] = c1.y;
        }
#pragma unroll
        for (int b = 0; b < BT; b++) {
            const uint2 uu2 = u2p[(size_t)(b0 + b) * Rc + r];
            const float2 u01 = up2(uu2.x), u23 = up2(uu2.y);
            float h[Oc];
#pragma unroll
            for (int o = 0; o < Oc; o++)
                h[o] = w[o][0] * u01.x + w[o][1] * u01.y
                     + w[o][2] * u23.x + w[o][3] * u23.y;
            uint4 pkv;
            pkv.x = pk2(h[0], h[1]);
            pkv.y = pk2(h[2], h[3]);
            pkv.z = pk2(h[4], h[5]);
            pkv.w = pk2(h[6], h[7]);
            uh[b * Rc + r] = pkv;
        }
    }
    __syncthreads();        // the only barrier

    // ============== routing: warp b owns batch b, fully warp-private ===========
    if (warp < BT) {
        const uint4* __restrict__ base = uh + warp * Rc + lane;

        // ---- pass 0 (half2 accumulate): s0 = mean_r u_hat ; v0 = squash ----
        // fp16 accumulation only perturbs the iter-0 softmax weights (harmless).
        unsigned int h0 = 0u, h1 = 0u, h2v = 0u, h3 = 0u;
#pragma unroll 9
        for (int i = 0; i < RW; i++) {
            const uint4 v = base[i * 32];
            h0 = hadd2u(h0, v.x); h1 = hadd2u(h1, v.y);
            h2v = hadd2u(h2v, v.z); h3 = hadd2u(h3, v.w);
        }
#pragma unroll
        for (int s = 16; s; s >>= 1) {
            h0 = hadd2u(h0, __shfl_xor_sync(0xffffffffu, h0, s));
            h1 = hadd2u(h1, __shfl_xor_sync(0xffffffffu, h1, s));
            h2v = hadd2u(h2v, __shfl_xor_sync(0xffffffffu, h2v, s));
            h3 = hadd2u(h3, __shfl_xor_sync(0xffffffffu, h3, s));
        }
        float v0[Oc];    // true v0 (for vs construction)
        float v0s[Oc];   // v0 * log2(e) (for exp2-based softmax dot)
        {
            const float2 f0 = up2(h0), f1 = up2(h1), f2 = up2(h2v), f3 = up2(h3);
            float s[Oc] = { f0.x, f0.y, f1.x, f1.y, f2.x, f2.y, f3.x, f3.y };
            float sq = 0.f;
#pragma unroll
            for (int o = 0; o < Oc; o++) { s[o] *= (1.0f / (float)Rc); sq += s[o] * s[o]; }
            const float scl = sqrtf(sq) / (1.f + sq);
#pragma unroll
            for (int o = 0; o < Oc; o++) {
                v0[o]  = s[o] * scl;
                v0s[o] = v0[o] * LOG2E;
            }
        }

        // ---- pass 1: e = 2^(<uh,v0s>) ; weighted sums -> v1 (R13 form) ----
        float p[9];
#pragma unroll
        for (int q = 0; q < 9; q++) p[q] = 0.f;
#pragma unroll 9
        for (int i = 0; i < RW; i++) {
            const uint4 v = base[i * 32];
            const float2 f0 = up2(v.x), f1 = up2(v.y), f2 = up2(v.z), f3 = up2(v.w);
            const float a = f0.x * v0s[0] + f0.y * v0s[1] + f1.x * v0s[2] + f1.y * v0s[3]
                          + f2.x * v0s[4] + f2.y * v0s[5] + f3.x * v0s[6] + f3.y * v0s[7];
            const float e = ex2f(a);
            p[8] += e;
            p[0] += e * f0.x; p[1] += e * f0.y;
            p[2] += e * f1.x; p[3] += e * f1.y;
            p[4] += e * f2.x; p[5] += e * f2.y;
            p[6] += e * f3.x; p[7] += e * f3.y;
        }
        wredN<9>(p);
        float vss[Oc];  // (v0 + v1) * log2(e)   [b2 = <uh, v0+v1>]
        {
            const float inv = __fdividef(1.f, p[8]);
            float sq = 0.f;
#pragma unroll
            for (int o = 0; o < Oc; o++) { p[o] *= inv; sq += p[o] * p[o]; }
            const float scl = sqrtf(sq) / (1.f + sq);
#pragma unroll
            for (int o = 0; o < Oc; o++) vss[o] = (v0[o] + p[o] * scl) * LOG2E;
        }

        // ---- pass 2: e = 2^(<uh,vss>) ; weighted sums -> v2 -> out ----
#pragma unroll
        for (int q = 0; q < 9; q++) p[q] = 0.f;
#pragma unroll 9
        for (int i = 0; i < RW; i++) {
            const uint4 v = base[i * 32];
            const float2 f0 = up2(v.x), f1 = up2(v.y), f2 = up2(v.z), f3 = up2(v.w);
            const float a = f0.x * vss[0] + f0.y * vss[1] + f1.x * vss[2] + f1.y * vss[3]
                          + f2.x * vss[4] + f2.y * vss[5] + f3.x * vss[6] + f3.y * vss[7];
            const float e = ex2f(a);
            p[8] += e;
            p[0] += e * f0.x; p[1] += e * f0.y;
            p[2] += e * f1.x; p[3] += e * f1.y;
            p[4] += e * f2.x; p[5] += e * f2.y;
            p[6] += e * f3.x; p[7] += e * f3.y;
        }
        wredN<9>(p);
        {
            const float inv = __fdividef(1.f, p[8]);
            float sq = 0.f;
#pragma unroll
            for (int o = 0; o < Oc; o++) { p[o] *= inv; sq += p[o] * p[o]; }
            const float scl = sqrtf(sq) / (1.f + sq);
            if (lane < Oc)
                out[((size_t)(b0 + warp) * Jc + j) * Oc + lane] = p[lane] * scl;
        }
    }
}

extern "C" void kernel_launch(void* const* d_in, const int* in_sizes, int n_in,
                              void* d_out, int out_size)
{
    const float* u = (const float*)d_in[0];
    const float* W = (const float*)d_in[1];
    if (n_in >= 2 && in_sizes[0] > in_sizes[1]) {   // defensive order check
        const float* tmp = u; u = W; W = tmp;
    }

    cudaFuncSetAttribute(digitcaps_kernel,
                         cudaFuncAttributeMaxDynamicSharedMemorySize, SMEM_BYTES);

    // 1) convert W, u to fp16 staging buffers
    prep_kernel<<<(W_ELEMS / 8 + 255) / 256, 256>>>(W, u);
    // 2) fused capsule-routing kernel
    dim3 grid(Bc / BT, Jc);   // (16, 166)
    digitcaps_kernel<<<grid, TT, SMEM_BYTES>>>((float*)d_out);
}